// round 4
// baseline (speedup 1.0000x reference)
#include <cuda_runtime.h>
#include <cuda_bf16.h>
#include <math.h>

// N=100000, E=1600000, D=OUT=128
#define MAX_N 100000
#define D_DIM 128
#define SROW 132            // smem row stride (floats): 132*4B = 528B, 16B-aligned rows

// Scratch (device globals — allocation-free)
__device__ float g_escore[MAX_N];     // exp(feature @ w_gate)
__device__ int   g_seg[MAX_N + 1];    // segment starts in sorted dst

// ---------------------------------------------------------------------------
// packed f32x2 helpers (Blackwell FFMA2 path — 2x fp32 FMA throughput)
// ---------------------------------------------------------------------------
__device__ __forceinline__ unsigned long long pack2(float lo, float hi) {
    unsigned long long r;
    asm("mov.b64 %0, {%1, %2};" : "=l"(r) : "f"(lo), "f"(hi));
    return r;
}
__device__ __forceinline__ unsigned long long dup2(float v) {
    unsigned long long r;
    asm("mov.b64 %0, {%1, %1};" : "=l"(r) : "f"(v));
    return r;
}
__device__ __forceinline__ void fma2(unsigned long long& d,
                                     unsigned long long a, unsigned long long b) {
    asm("fma.rn.f32x2 %0, %1, %2, %0;" : "+l"(d) : "l"(a), "l"(b));
}
__device__ __forceinline__ float2 unpack2(unsigned long long p) {
    float lo, hi;
    asm("mov.b64 {%0, %1}, %2;" : "=f"(lo), "=f"(hi) : "l"(p));
    return make_float2(lo, hi);
}

// ---------------------------------------------------------------------------
// K1: escore[n] = exp(feature[n] . w_gate)  (warp per 4 nodes, MLP=4)
//     + segment starts via binary search on sorted dst
// ---------------------------------------------------------------------------
__device__ __forceinline__ int lower_bound_dev(const int* __restrict__ a, int n, int key) {
    int lo = 0, hi = n;
    while (lo < hi) {
        int mid = (lo + hi) >> 1;
        if (a[mid] < key) lo = mid + 1; else hi = mid;
    }
    return lo;
}

__global__ __launch_bounds__(256) void k1_score_seg(
    const float* __restrict__ feature,
    const int*   __restrict__ dst,
    const float* __restrict__ w_gate,
    int N, int E)
{
    int warp = blockIdx.x * 8 + (threadIdx.x >> 5);
    int lane = threadIdx.x & 31;
    int n0 = warp * 4;
    if (n0 < N) {
        float4 g = ((const float4*)w_gate)[lane];
        int i0 = n0, i1 = min(n0 + 1, N - 1), i2 = min(n0 + 2, N - 1), i3 = min(n0 + 3, N - 1);
        float4 f0 = ((const float4*)(feature + (size_t)i0 * D_DIM))[lane];
        float4 f1 = ((const float4*)(feature + (size_t)i1 * D_DIM))[lane];
        float4 f2 = ((const float4*)(feature + (size_t)i2 * D_DIM))[lane];
        float4 f3 = ((const float4*)(feature + (size_t)i3 * D_DIM))[lane];
        float p0 = f0.x*g.x + f0.y*g.y + f0.z*g.z + f0.w*g.w;
        float p1 = f1.x*g.x + f1.y*g.y + f1.z*g.z + f1.w*g.w;
        float p2 = f2.x*g.x + f2.y*g.y + f2.z*g.z + f2.w*g.w;
        float p3 = f3.x*g.x + f3.y*g.y + f3.z*g.z + f3.w*g.w;
        #pragma unroll
        for (int o = 16; o; o >>= 1) {
            p0 += __shfl_xor_sync(0xFFFFFFFFu, p0, o);
            p1 += __shfl_xor_sync(0xFFFFFFFFu, p1, o);
            p2 += __shfl_xor_sync(0xFFFFFFFFu, p2, o);
            p3 += __shfl_xor_sync(0xFFFFFFFFu, p3, o);
        }
        if (lane < 4) {
            float pv = (lane == 0) ? p0 : (lane == 1) ? p1 : (lane == 2) ? p2 : p3;
            int n = n0 + lane;
            if (n < N) g_escore[n] = expf(pv);
        }
    }
    int gt = blockIdx.x * 256 + threadIdx.x;
    if (gt <= N) g_seg[gt] = lower_bound_dev(dst, E, gt);
}

// ---------------------------------------------------------------------------
// K23 (fused): per-block 128 nodes.
//   Phase 1: warp-per-node segment softmax + weighted feature aggregation,
//            rows written TRANSPOSED into smem As[k][m] (stride SROW).
//   Phase 2: 128x128x128 GEMM out = As^T @ W with packed f32x2 FMAs.
// ---------------------------------------------------------------------------
__global__ __launch_bounds__(256, 2) void k23_fused(
    const float* __restrict__ feature,
    const int*   __restrict__ src,
    const float* __restrict__ W,      // w_feat [128][128] row-major
    float* __restrict__ out,
    int N)
{
    extern __shared__ float AsF[];    // [128][SROW]
    int tid  = threadIdx.x;
    int lane = tid & 31;
    int wid  = tid >> 5;              // 0..7
    int row0 = blockIdx.x * 128;

    // ---------------- Phase 1: aggregation ----------------
    for (int i = 0; i < 16; ++i) {
        int m = wid * 16 + i;         // local row 0..127
        int n = row0 + m;
        int s = 0, t = 0;
        if (n < N) { s = g_seg[n]; t = g_seg[n + 1]; }

        float a0 = 0.f, a1 = 0.f, a2 = 0.f, a3 = 0.f, dsum = 0.f;
        for (int base = s; base < t; base += 32) {
            int e = base + lane;
            bool v = e < t;
            int   sv = v ? src[e] : 0;
            float we = v ? __ldg(g_escore + sv) : 0.f;
            dsum += we;
            int cnt = min(32, t - base);
            #pragma unroll 4
            for (int j = 0; j < cnt; ++j) {
                float wj = __shfl_sync(0xFFFFFFFFu, we, j);
                int   sj = __shfl_sync(0xFFFFFFFFu, sv, j);
                const float* fr = feature + (size_t)sj * D_DIM;
                a0 = fmaf(wj, __ldg(fr + lane),      a0);
                a1 = fmaf(wj, __ldg(fr + lane + 32), a1);
                a2 = fmaf(wj, __ldg(fr + lane + 64), a2);
                a3 = fmaf(wj, __ldg(fr + lane + 96), a3);
            }
        }
        #pragma unroll
        for (int o = 16; o; o >>= 1) dsum += __shfl_xor_sync(0xFFFFFFFFu, dsum, o);
        float inv = (t > s) ? 1.f / dsum : 0.f;

        AsF[(lane)      * SROW + m] = a0 * inv;
        AsF[(lane + 32) * SROW + m] = a1 * inv;
        AsF[(lane + 64) * SROW + m] = a2 * inv;
        AsF[(lane + 96) * SROW + m] = a3 * inv;
    }
    __syncthreads();

    // ---------------- Phase 2: GEMM (f32x2) ----------------
    int tr = tid >> 4;                // 0..15: row group (8 rows)
    int tc = tid & 15;                // 0..15: col group (8 cols)

    unsigned long long acc[8][4];
    #pragma unroll
    for (int i = 0; i < 8; ++i)
        #pragma unroll
        for (int j = 0; j < 4; ++j) acc[i][j] = 0ULL;

    const float* wbase = W + tc * 8;
    #pragma unroll 4
    for (int k = 0; k < 128; ++k) {
        float4 alo = *(const float4*)&AsF[k * SROW + tr * 8];
        float4 ahi = *(const float4*)&AsF[k * SROW + tr * 8 + 4];
        float4 wlo = __ldg((const float4*)(wbase + k * 128));
        float4 whi = __ldg((const float4*)(wbase + k * 128 + 4));

        unsigned long long wp[4];
        wp[0] = pack2(wlo.x, wlo.y);  wp[1] = pack2(wlo.z, wlo.w);
        wp[2] = pack2(whi.x, whi.y);  wp[3] = pack2(whi.z, whi.w);

        unsigned long long ap[8];
        ap[0] = dup2(alo.x); ap[1] = dup2(alo.y); ap[2] = dup2(alo.z); ap[3] = dup2(alo.w);
        ap[4] = dup2(ahi.x); ap[5] = dup2(ahi.y); ap[6] = dup2(ahi.z); ap[7] = dup2(ahi.w);

        #pragma unroll
        for (int i = 0; i < 8; ++i)
            #pragma unroll
            for (int j = 0; j < 4; ++j)
                fma2(acc[i][j], ap[i], wp[j]);
    }

    #pragma unroll
    for (int i = 0; i < 8; ++i) {
        int row = row0 + tr * 8 + i;
        if (row < N) {
            float2 c0 = unpack2(acc[i][0]);
            float2 c1 = unpack2(acc[i][1]);
            float2 c2 = unpack2(acc[i][2]);
            float2 c3 = unpack2(acc[i][3]);
            float* o = out + (size_t)row * 128 + tc * 8;
            *(float4*)(o)     = make_float4(c0.x, c0.y, c1.x, c1.y);
            *(float4*)(o + 4) = make_float4(c2.x, c2.y, c3.x, c3.y);
        }
    }
}

// ---------------------------------------------------------------------------
extern "C" void kernel_launch(void* const* d_in, const int* in_sizes, int n_in,
                              void* d_out, int out_size)
{
    const float* feature = (const float*)d_in[0];
    const int*   src     = (const int*)  d_in[1];
    const int*   dst     = (const int*)  d_in[2];
    const float* w_gate  = (const float*)d_in[3];
    const float* w_feat  = (const float*)d_in[4];
    float*       out     = (float*)d_out;

    int N = in_sizes[0] / D_DIM;
    int E = in_sizes[1];

    const int SMEM = 128 * SROW * 4;   // 67,584 B
    cudaFuncSetAttribute(k23_fused, cudaFuncAttributeMaxDynamicSharedMemorySize, SMEM);

    // K1: 4 nodes per warp + segment bounds
    int warps1  = (N + 3) / 4;
    int blocks1 = (warps1 + 7) / 8;
    int blocks1_min = (N + 1 + 255) / 256;
    if (blocks1 < blocks1_min) blocks1 = blocks1_min;
    k1_score_seg<<<blocks1, 256>>>(feature, dst, w_gate, N, E);

    // K23: fused aggregate + GEMM, 128 nodes per block
    int blocks2 = (N + 127) / 128;
    k23_fused<<<blocks2, 256, SMEM>>>(feature, src, w_feat, out, N);
}

// round 5
// speedup vs baseline: 1.9135x; 1.9135x over previous
#include <cuda_runtime.h>
#include <cuda_fp16.h>
#include <math.h>

// N=100000, E=1600000, D=OUT=128
#define MAX_N 100000
#define D_DIM 128
#define PAD_N 100096                 // padded to 128 for GEMM tiles

// Scratch (device globals — allocation-free)
__device__ float  g_escore[MAX_N];              // exp(feature @ w_gate)
__device__ int    g_seg[MAX_N + 1];             // segment starts in sorted dst
__device__ __half g_G[(size_t)PAD_N * D_DIM];   // fp16(feature @ w_feat)

// ---------------------------------------------------------------------------
// K1: escore[n] = exp(feature[n] . w_gate)  (warp per 4 nodes)
//     + segment starts via binary search on sorted dst
// ---------------------------------------------------------------------------
__device__ __forceinline__ int lower_bound_dev(const int* __restrict__ a, int n, int key) {
    int lo = 0, hi = n;
    while (lo < hi) {
        int mid = (lo + hi) >> 1;
        if (a[mid] < key) lo = mid + 1; else hi = mid;
    }
    return lo;
}

__global__ __launch_bounds__(256) void k1_score_seg(
    const float* __restrict__ feature,
    const int*   __restrict__ dst,
    const float* __restrict__ w_gate,
    int N, int E)
{
    int warp = blockIdx.x * 8 + (threadIdx.x >> 5);
    int lane = threadIdx.x & 31;
    int n0 = warp * 4;
    if (n0 < N) {
        float4 g = ((const float4*)w_gate)[lane];
        int i0 = n0, i1 = min(n0 + 1, N - 1), i2 = min(n0 + 2, N - 1), i3 = min(n0 + 3, N - 1);
        float4 f0 = ((const float4*)(feature + (size_t)i0 * D_DIM))[lane];
        float4 f1 = ((const float4*)(feature + (size_t)i1 * D_DIM))[lane];
        float4 f2 = ((const float4*)(feature + (size_t)i2 * D_DIM))[lane];
        float4 f3 = ((const float4*)(feature + (size_t)i3 * D_DIM))[lane];
        float p0 = f0.x*g.x + f0.y*g.y + f0.z*g.z + f0.w*g.w;
        float p1 = f1.x*g.x + f1.y*g.y + f1.z*g.z + f1.w*g.w;
        float p2 = f2.x*g.x + f2.y*g.y + f2.z*g.z + f2.w*g.w;
        float p3 = f3.x*g.x + f3.y*g.y + f3.z*g.z + f3.w*g.w;
        #pragma unroll
        for (int o = 16; o; o >>= 1) {
            p0 += __shfl_xor_sync(0xFFFFFFFFu, p0, o);
            p1 += __shfl_xor_sync(0xFFFFFFFFu, p1, o);
            p2 += __shfl_xor_sync(0xFFFFFFFFu, p2, o);
            p3 += __shfl_xor_sync(0xFFFFFFFFu, p3, o);
        }
        if (lane < 4) {
            float pv = (lane == 0) ? p0 : (lane == 1) ? p1 : (lane == 2) ? p2 : p3;
            int n = n0 + lane;
            if (n < N) g_escore[n] = expf(pv);
        }
    }
    int gt = blockIdx.x * 256 + threadIdx.x;
    if (gt <= N) g_seg[gt] = lower_bound_dev(dst, E, gt);
}

// ---------------------------------------------------------------------------
// KG: G = fp16(feature @ W).  BM=128, BN=128(full), fp16 HMMA (mma.sync
//     m16n8k16, fp32 accumulate). 8 warps as 4(m) x 2(n), warp tile 32x64.
// ---------------------------------------------------------------------------
#define KG_PAD 136   // half-element row stride in smem (272B: conflict-free frags)

__global__ __launch_bounds__(256) void kg_gemm(
    const float* __restrict__ feature,
    const float* __restrict__ W,
    __half* __restrict__ G,
    int N)
{
    extern __shared__ __half sh[];
    __half* Ah = sh;                     // [128][KG_PAD]  A tile (m-major, k contig)
    __half* Wt = sh + 128 * KG_PAD;      // [128][KG_PAD]  W^T   (n-major, k contig)
    int tid = threadIdx.x;
    int row0 = blockIdx.x * 128;

    // Load & transpose W -> Wt[n][k] as fp16
    #pragma unroll
    for (int q = tid; q < 128 * 32; q += 256) {
        int k  = q >> 5;
        int n4 = (q & 31) * 4;
        float4 w = __ldg((const float4*)(W + k * 128 + n4));
        Wt[(n4 + 0) * KG_PAD + k] = __float2half(w.x);
        Wt[(n4 + 1) * KG_PAD + k] = __float2half(w.y);
        Wt[(n4 + 2) * KG_PAD + k] = __float2half(w.z);
        Wt[(n4 + 3) * KG_PAD + k] = __float2half(w.w);
    }
    // Load A tile (row-clamped), convert to fp16
    #pragma unroll
    for (int q = tid; q < 128 * 32; q += 256) {
        int r  = q >> 5;
        int c4 = (q & 31) * 4;
        int row = row0 + r; if (row >= N) row = N - 1;
        float4 f = __ldg((const float4*)(feature + (size_t)row * 128 + c4));
        __half2* p = (__half2*)(Ah + r * KG_PAD + c4);
        p[0] = __floats2half2_rn(f.x, f.y);
        p[1] = __floats2half2_rn(f.z, f.w);
    }
    __syncthreads();

    int wid = tid >> 5, lane = tid & 31;
    int warp_m = wid >> 1;          // 0..3
    int warp_n = wid & 1;           // 0..1
    int gid = lane >> 2;            // 0..7
    int tig = lane & 3;             // 0..3

    float c[2][8][4];
    #pragma unroll
    for (int mi = 0; mi < 2; ++mi)
        #pragma unroll
        for (int ni = 0; ni < 8; ++ni)
            #pragma unroll
            for (int x = 0; x < 4; ++x) c[mi][ni][x] = 0.f;

    #pragma unroll
    for (int k0 = 0; k0 < 128; k0 += 16) {
        unsigned a[2][4];
        #pragma unroll
        for (int mi = 0; mi < 2; ++mi) {
            const __half* base = Ah + (warp_m * 32 + mi * 16 + gid) * KG_PAD + k0 + tig * 2;
            a[mi][0] = *(const unsigned*)(base);
            a[mi][1] = *(const unsigned*)(base + 8 * KG_PAD);
            a[mi][2] = *(const unsigned*)(base + 8);
            a[mi][3] = *(const unsigned*)(base + 8 * KG_PAD + 8);
        }
        #pragma unroll
        for (int ni = 0; ni < 8; ++ni) {
            const __half* bb = Wt + (warp_n * 64 + ni * 8 + gid) * KG_PAD + k0 + tig * 2;
            unsigned b0 = *(const unsigned*)(bb);
            unsigned b1 = *(const unsigned*)(bb + 8);
            #pragma unroll
            for (int mi = 0; mi < 2; ++mi) {
                asm volatile(
                    "mma.sync.aligned.m16n8k16.row.col.f32.f16.f16.f32 "
                    "{%0,%1,%2,%3}, {%4,%5,%6,%7}, {%8,%9}, {%0,%1,%2,%3};"
                    : "+f"(c[mi][ni][0]), "+f"(c[mi][ni][1]),
                      "+f"(c[mi][ni][2]), "+f"(c[mi][ni][3])
                    : "r"(a[mi][0]), "r"(a[mi][1]), "r"(a[mi][2]), "r"(a[mi][3]),
                      "r"(b0), "r"(b1));
            }
        }
    }

    // Store G in fp16 (half2 per fragment row)
    #pragma unroll
    for (int mi = 0; mi < 2; ++mi) {
        #pragma unroll
        for (int ni = 0; ni < 8; ++ni) {
            int m  = warp_m * 32 + mi * 16 + gid;
            int nn = warp_n * 64 + ni * 8 + tig * 2;
            int row = row0 + m;
            if (row < N)
                *(__half2*)(G + (size_t)row * 128 + nn) =
                    __floats2half2_rn(c[mi][ni][0], c[mi][ni][1]);
            if (row + 8 < N)
                *(__half2*)(G + (size_t)(row + 8) * 128 + nn) =
                    __floats2half2_rn(c[mi][ni][2], c[mi][ni][3]);
        }
    }
}

// ---------------------------------------------------------------------------
// K2: per-node (warp) segment softmax over escore + weighted sum of fp16 G
//     rows, write fp32 out. No atomics (dst sorted -> contiguous segments).
// ---------------------------------------------------------------------------
__global__ __launch_bounds__(256) void k2_out(
    const __half* __restrict__ G,
    const int*    __restrict__ src,
    float* __restrict__ out,
    int N)
{
    int warp = (blockIdx.x * blockDim.x + threadIdx.x) >> 5;
    int lane = threadIdx.x & 31;
    if (warp >= N) return;

    int s = g_seg[warp];
    int t = g_seg[warp + 1];

    float4 acc = make_float4(0.f, 0.f, 0.f, 0.f);
    float dsum = 0.f;
    for (int base = s; base < t; base += 32) {
        int e = base + lane;
        bool v = e < t;
        int   sv = v ? src[e] : 0;
        float we = v ? __ldg(g_escore + sv) : 0.f;
        dsum += we;
        int cnt = min(32, t - base);
        #pragma unroll 4
        for (int j = 0; j < cnt; ++j) {
            float wj = __shfl_sync(0xFFFFFFFFu, we, j);
            int   sj = __shfl_sync(0xFFFFFFFFu, sv, j);
            uint2 hv = __ldg((const uint2*)(G + (size_t)sj * 128) + lane);
            float2 f0 = __half22float2(*(__half2*)&hv.x);
            float2 f1 = __half22float2(*(__half2*)&hv.y);
            acc.x = fmaf(wj, f0.x, acc.x);
            acc.y = fmaf(wj, f0.y, acc.y);
            acc.z = fmaf(wj, f1.x, acc.z);
            acc.w = fmaf(wj, f1.y, acc.w);
        }
    }
    #pragma unroll
    for (int o = 16; o; o >>= 1) dsum += __shfl_xor_sync(0xFFFFFFFFu, dsum, o);

    float inv = (t > s) ? 1.f / dsum : 0.f;
    acc.x *= inv; acc.y *= inv; acc.z *= inv; acc.w *= inv;
    // lane owns out dims [4*lane, 4*lane+4)
    ((float4*)(out + (size_t)warp * 128))[lane] = acc;
}

// ---------------------------------------------------------------------------
extern "C" void kernel_launch(void* const* d_in, const int* in_sizes, int n_in,
                              void* d_out, int out_size)
{
    const float* feature = (const float*)d_in[0];
    const int*   src     = (const int*)  d_in[1];
    const int*   dst     = (const int*)  d_in[2];
    const float* w_gate  = (const float*)d_in[3];
    const float* w_feat  = (const float*)d_in[4];
    float*       out     = (float*)d_out;

    int N = in_sizes[0] / D_DIM;
    int E = in_sizes[1];

    __half* g_G_ptr = nullptr;
    cudaGetSymbolAddress((void**)&g_G_ptr, g_G);

    const int SMEM_KG = 2 * 128 * KG_PAD * (int)sizeof(__half);   // 69,632 B
    cudaFuncSetAttribute(kg_gemm, cudaFuncAttributeMaxDynamicSharedMemorySize, SMEM_KG);

    // K1: gate scores (4 nodes/warp) + segment bounds
    int warps1  = (N + 3) / 4;
    int blocks1 = (warps1 + 7) / 8;
    int blocks1_min = (N + 1 + 255) / 256;
    if (blocks1 < blocks1_min) blocks1 = blocks1_min;
    k1_score_seg<<<blocks1, 256>>>(feature, dst, w_gate, N, E);

    // KG: G = fp16(feature @ w_feat), 128 rows per block
    int blocksG = (N + 127) / 128;
    kg_gemm<<<blocksG, 256, SMEM_KG>>>(feature, w_feat, g_G_ptr, N);

    // K2: warp per node, softmax-weighted gather of G -> out
    int blocks2 = (N * 32 + 255) / 256;
    k2_out<<<blocks2, 256>>>(g_G_ptr, src, out, N);
}